// round 2
// baseline (speedup 1.0000x reference)
#include <cuda_runtime.h>
#include <cstdint>
#include <cstddef>

// ============================================================================
// SpanMarkerV1: start/end MLP projections -> span gather -> output MLP
//   B=8, L=512, D=768, S=6144, H=3072
// GEMMs: mma.sync m16n8k8 tf32 (fp32 accum), 2-stage cp.async pipeline.
// ============================================================================

#define BM 128
#define BN 128
#define BK 32
#define AS_STRIDE 36    // 128x36 floats, pad avoids 8-way A-frag conflicts; 144B row = 16B-aligned
#define BS_STRIDE 132   // 32x132 floats, 528B row = 16B-aligned
#define STAGE_FLOATS (BM * AS_STRIDE + BK * BS_STRIDE)   // 8832
#define SMEM_BYTES (2 * STAGE_FLOATS * 4)                // 70656

// -------- scratch (device globals; allocations are forbidden) ---------------
__device__ float g_hidden[150994944ULL]; // 49152*3072  (604 MB), reused
__device__ float g_srep[3145728ULL];     // 4096*768
__device__ float g_erep[3145728ULL];     // 4096*768
__device__ float g_cat[75497472ULL];     // 49152*1536  (302 MB)

__device__ __forceinline__ uint32_t f2tf32(float x) {
    uint32_t r;
    asm("cvt.rna.tf32.f32 %0, %1;" : "=r"(r) : "f"(x));
    return r;
}

__device__ __forceinline__ void cp16(void* smem_ptr, const void* gmem_ptr) {
    uint32_t s = (uint32_t)__cvta_generic_to_shared(smem_ptr);
    asm volatile("cp.async.cg.shared.global [%0], [%1], 16;\n" :: "r"(s), "l"(gmem_ptr));
}

__device__ __forceinline__ void mma_tf32(float c[4], const uint32_t a[4], const uint32_t b[2]) {
    asm volatile(
        "mma.sync.aligned.m16n8k8.row.col.f32.tf32.tf32.f32 "
        "{%0,%1,%2,%3}, {%4,%5,%6,%7}, {%8,%9}, {%0,%1,%2,%3};\n"
        : "+f"(c[0]), "+f"(c[1]), "+f"(c[2]), "+f"(c[3])
        : "r"(a[0]), "r"(a[1]), "r"(a[2]), "r"(a[3]),
          "r"(b[0]), "r"(b[1]));
}

// C[M,N] = act(A[M,K] @ B[K,N] + bias)   A,B,C row-major; all dims % tile == 0
__global__ __launch_bounds__(256, 1)
void gemm_tf32_kernel(const float* __restrict__ A, const float* __restrict__ B,
                      const float* __restrict__ bias, float* __restrict__ C,
                      int M, int N, int K, int do_relu)
{
    extern __shared__ float smem[];

    const int tid  = threadIdx.x;
    const int warp = tid >> 5;
    const int lane = tid & 31;
    const int wm = warp & 3;   // 0..3 -> 32-row warp tile
    const int wn = warp >> 2;  // 0..1 -> 64-col warp tile
    const int tileM = blockIdx.y * BM;
    const int tileN = blockIdx.x * BN;

    float acc[2][8][4];
#pragma unroll
    for (int mi = 0; mi < 2; mi++)
#pragma unroll
        for (int ni = 0; ni < 8; ni++)
#pragma unroll
            for (int j = 0; j < 4; j++) acc[mi][ni][j] = 0.0f;

    const int KT = K / BK;

    // ---- async stage loader: A tile 128x32, B tile 32x128 (8 x cp16/thread) --
    auto load_stage = [&](int s, int k0) {
        float* As_ = smem + s * STAGE_FLOATS;
        float* Bs_ = As_ + BM * AS_STRIDE;
#pragma unroll
        for (int i = 0; i < 4; i++) {
            int f4  = tid + i * 256;
            int row = f4 >> 3;           // 0..127
            int c4  = (f4 & 7) << 2;     // 0..28
            cp16(&As_[row * AS_STRIDE + c4], &A[(size_t)(tileM + row) * K + k0 + c4]);
        }
#pragma unroll
        for (int i = 0; i < 4; i++) {
            int f4  = tid + i * 256;
            int row = f4 >> 5;           // 0..31
            int c4  = (f4 & 31) << 2;    // 0..124
            cp16(&Bs_[row * BS_STRIDE + c4], &B[(size_t)(k0 + row) * N + tileN + c4]);
        }
        asm volatile("cp.async.commit_group;\n" ::);
    };

    load_stage(0, 0);

    for (int kt = 0; kt < KT; kt++) {
        const bool more = (kt + 1 < KT);
        if (more) load_stage((kt + 1) & 1, (kt + 1) * BK);

        if (more) asm volatile("cp.async.wait_group 1;\n" ::);
        else      asm volatile("cp.async.wait_group 0;\n" ::);
        __syncthreads();

        const float* As_ = smem + (kt & 1) * STAGE_FLOATS;
        const float* Bs_ = As_ + BM * AS_STRIDE;

#pragma unroll
        for (int kk = 0; kk < BK; kk += 8) {
            uint32_t afrag[2][4], bfrag[8][2];
            const int mrow = wm * 32 + (lane >> 2);
            const int kcol = kk + (lane & 3);
#pragma unroll
            for (int mi = 0; mi < 2; mi++) {
                int m0 = mrow + mi * 16;
                afrag[mi][0] = f2tf32(As_[(m0    ) * AS_STRIDE + kcol    ]);
                afrag[mi][1] = f2tf32(As_[(m0 + 8) * AS_STRIDE + kcol    ]);
                afrag[mi][2] = f2tf32(As_[(m0    ) * AS_STRIDE + kcol + 4]);
                afrag[mi][3] = f2tf32(As_[(m0 + 8) * AS_STRIDE + kcol + 4]);
            }
#pragma unroll
            for (int ni = 0; ni < 8; ni++) {
                int n0 = wn * 64 + ni * 8 + (lane >> 2);
                bfrag[ni][0] = f2tf32(Bs_[(kcol    ) * BS_STRIDE + n0]);
                bfrag[ni][1] = f2tf32(Bs_[(kcol + 4) * BS_STRIDE + n0]);
            }
#pragma unroll
            for (int mi = 0; mi < 2; mi++)
#pragma unroll
                for (int ni = 0; ni < 8; ni++)
                    mma_tf32(acc[mi][ni], afrag[mi], bfrag[ni]);
        }
        __syncthreads();
    }

    // ---- epilogue: bias + optional relu ----
#pragma unroll
    for (int mi = 0; mi < 2; mi++) {
#pragma unroll
        for (int ni = 0; ni < 8; ni++) {
            int m = tileM + wm * 32 + mi * 16 + (lane >> 2);
            int n = tileN + wn * 64 + ni * 8 + ((lane & 3) << 1);
            float b0 = bias[n], b1 = bias[n + 1];
            float v0 = acc[mi][ni][0] + b0;
            float v1 = acc[mi][ni][1] + b1;
            float v2 = acc[mi][ni][2] + b0;
            float v3 = acc[mi][ni][3] + b1;
            if (do_relu) {
                v0 = fmaxf(v0, 0.0f); v1 = fmaxf(v1, 0.0f);
                v2 = fmaxf(v2, 0.0f); v3 = fmaxf(v3, 0.0f);
            }
            *(float2*)&C[(size_t)m * N + n]       = make_float2(v0, v1);
            *(float2*)&C[(size_t)(m + 8) * N + n] = make_float2(v2, v3);
        }
    }
}

// gather spans + concat + relu: cat[r,0:768]=relu(srep[b,i0]); cat[r,768:1536]=relu(erep[b,i1])
__global__ void gather_cat_kernel(const float* __restrict__ srep, const float* __restrict__ erep,
                                  const int* __restrict__ span, float* __restrict__ cat)
{
    const int r  = blockIdx.x;     // 0..49151  (b*6144 + s)
    const int c4 = threadIdx.x;    // 0..383 (384 float4 = 1536 floats)
    const int b  = r / 6144;

    float4 v;
    if (c4 < 192) {
        int i0 = span[((size_t)r << 1) + 0];
        v = *(const float4*)&srep[((size_t)(b * 512 + i0)) * 768 + (c4 << 2)];
    } else {
        int i1 = span[((size_t)r << 1) + 1];
        v = *(const float4*)&erep[((size_t)(b * 512 + i1)) * 768 + ((c4 - 192) << 2)];
    }
    v.x = fmaxf(v.x, 0.0f);
    v.y = fmaxf(v.y, 0.0f);
    v.z = fmaxf(v.z, 0.0f);
    v.w = fmaxf(v.w, 0.0f);
    *(float4*)&cat[(size_t)r * 1536 + (c4 << 2)] = v;
}

extern "C" void kernel_launch(void* const* d_in, const int* in_sizes, int n_in,
                              void* d_out, int out_size)
{
    const float* h    = (const float*)d_in[0];
    const int*   span = (const int*)  d_in[1];
    const float* sw1  = (const float*)d_in[2];
    const float* sb1  = (const float*)d_in[3];
    const float* sw2  = (const float*)d_in[4];
    const float* sb2  = (const float*)d_in[5];
    const float* ew1  = (const float*)d_in[6];
    const float* eb1  = (const float*)d_in[7];
    const float* ew2  = (const float*)d_in[8];
    const float* eb2  = (const float*)d_in[9];
    const float* ow1  = (const float*)d_in[10];
    const float* ob1  = (const float*)d_in[11];
    const float* ow2  = (const float*)d_in[12];
    const float* ob2  = (const float*)d_in[13];
    float* out = (float*)d_out;

    float *hidden, *srep, *erep, *cat;
    cudaGetSymbolAddress((void**)&hidden, g_hidden);
    cudaGetSymbolAddress((void**)&srep,   g_srep);
    cudaGetSymbolAddress((void**)&erep,   g_erep);
    cudaGetSymbolAddress((void**)&cat,    g_cat);

    static int smem_set = 0;
    if (!smem_set) {
        cudaFuncSetAttribute(gemm_tf32_kernel,
                             cudaFuncAttributeMaxDynamicSharedMemorySize, SMEM_BYTES);
        smem_set = 1;
    }

    const dim3 blk(256);

    // start projection: relu(h @ sw1 + sb1) @ sw2 + sb2
    gemm_tf32_kernel<<<dim3(3072 / BN, 4096 / BM), blk, SMEM_BYTES>>>(h,      sw1, sb1, hidden, 4096, 3072, 768,  1);
    gemm_tf32_kernel<<<dim3( 768 / BN, 4096 / BM), blk, SMEM_BYTES>>>(hidden, sw2, sb2, srep,   4096,  768, 3072, 0);
    // end projection
    gemm_tf32_kernel<<<dim3(3072 / BN, 4096 / BM), blk, SMEM_BYTES>>>(h,      ew1, eb1, hidden, 4096, 3072, 768,  1);
    gemm_tf32_kernel<<<dim3( 768 / BN, 4096 / BM), blk, SMEM_BYTES>>>(hidden, ew2, eb2, erep,   4096,  768, 3072, 0);
    // span gather + concat + relu
    gather_cat_kernel<<<49152, 384>>>(srep, erep, span, cat);
    // output projection: relu(cat @ ow1 + ob1) @ ow2 + ob2
    gemm_tf32_kernel<<<dim3(3072 / BN, 49152 / BM), blk, SMEM_BYTES>>>(cat,    ow1, ob1, hidden, 49152, 3072, 1536, 1);
    gemm_tf32_kernel<<<dim3( 768 / BN, 49152 / BM), blk, SMEM_BYTES>>>(hidden, ow2, ob2, out,    49152,  768, 3072, 0);
}

// round 5
// speedup vs baseline: 2.1272x; 2.1272x over previous
#include <cuda_runtime.h>
#include <cuda_fp16.h>
#include <cstdint>
#include <cstddef>

// ============================================================================
// SpanMarkerV1 on sm_100 (legacy tensor path): fp16 mma.sync m16n8k16, fp32 acc.
//   B=8, L=512, D=768, S=6144, H=3072
// All operands fp16 in gmem (same 11-bit significand as tf32 -> same accuracy
// as the passing tf32 kernel). 128x128x32 tiles, cp.async double buffer,
// conflict-free stride-40-half smem, 2 CTAs/SM.
// ============================================================================

#define BM 128
#define BN 128
#define BK 32
#define LSTR 40                      // smem row stride in halves (80B = 5x16B, conflict-free)
#define STAGE_H (BM * LSTR)          // 5120 halves per operand tile

// -------- scratch (device globals; allocations are forbidden) ---------------
__device__ __half g_hidden[150994944ULL]; // 49152*3072 fp16 (302 MB), reused
__device__ __half g_srep[3145728ULL];     // 4096*768
__device__ __half g_erep[3145728ULL];     // 4096*768
__device__ __half g_cat[75497472ULL];     // 49152*1536 (151 MB)
__device__ __half g_hh[3145728ULL];       // h in fp16
__device__ __half g_sw1t[2359296ULL];     // [3072,768]  = W^T [N,K]
__device__ __half g_ew1t[2359296ULL];
__device__ __half g_ow1t[4718592ULL];     // [3072,1536]
__device__ __half g_sw2t[2359296ULL];     // [768,3072]
__device__ __half g_ew2t[2359296ULL];
__device__ __half g_ow2t[2359296ULL];

__device__ __forceinline__ void cp16(void* smem_ptr, const void* gmem_ptr) {
    uint32_t s = (uint32_t)__cvta_generic_to_shared(smem_ptr);
    asm volatile("cp.async.cg.shared.global [%0], [%1], 16;\n" :: "r"(s), "l"(gmem_ptr));
}

__device__ __forceinline__ void mma_f16(float c[4], const uint32_t a[4], const uint32_t b[2]) {
    asm volatile(
        "mma.sync.aligned.m16n8k16.row.col.f32.f16.f16.f32 "
        "{%0,%1,%2,%3}, {%4,%5,%6,%7}, {%8,%9}, {%0,%1,%2,%3};\n"
        : "+f"(c[0]), "+f"(c[1]), "+f"(c[2]), "+f"(c[3])
        : "r"(a[0]), "r"(a[1]), "r"(a[2]), "r"(a[3]),
          "r"(b[0]), "r"(b[1]));
}

// ============================================================================
// C[M,N] = act(A[M,K] @ W + bias);  A fp16 [M,K], Bt = W^T fp16 [N,K].
// c_half: store fp16 (intermediates) else fp32 (final output).
// ============================================================================
__global__ __launch_bounds__(256, 2)
void gemm_f16(const __half* __restrict__ A, const __half* __restrict__ Bt,
              const float* __restrict__ bias, void* __restrict__ Cv,
              int M, int N, int K, int relu, int c_half)
{
    __shared__ __half As[2][STAGE_H];
    __shared__ __half Bs[2][STAGE_H];

    const int tid  = threadIdx.x;
    const int warp = tid >> 5;
    const int lane = tid & 31;
    const int wm = warp & 3;    // 32-row warp tile
    const int wn = warp >> 2;   // 64-col warp tile
    const int tileM = blockIdx.y * BM;
    const int tileN = blockIdx.x * BN;

    float acc[2][8][4];
#pragma unroll
    for (int mi = 0; mi < 2; mi++)
#pragma unroll
        for (int ni = 0; ni < 8; ni++)
#pragma unroll
            for (int j = 0; j < 4; j++) acc[mi][ni][j] = 0.0f;

    // per-thread staging coords: 512 chunks per tile, 2 per thread per operand
    const int r0 = tid >> 2;             // chunk row for ch = tid
    const int c0 = (tid & 3) << 3;       // halves offset (0,8,16,24)
    const int r1 = (tid + 256) >> 2;
    const int c1 = c0;

    auto stage = [&](int s, int k0) {
        cp16(&As[s][r0 * LSTR + c0], A + (size_t)(tileM + r0) * K + k0 + c0);
        cp16(&As[s][r1 * LSTR + c1], A + (size_t)(tileM + r1) * K + k0 + c1);
        cp16(&Bs[s][r0 * LSTR + c0], Bt + (size_t)(tileN + r0) * K + k0 + c0);
        cp16(&Bs[s][r1 * LSTR + c1], Bt + (size_t)(tileN + r1) * K + k0 + c1);
        asm volatile("cp.async.commit_group;\n" ::);
    };

    const int KT = K / BK;
    stage(0, 0);

    const int grow = lane >> 2;          // 0..7
    const int koff = (lane & 3) << 1;    // 0,2,4,6

    for (int kt = 0; kt < KT; kt++) {
        if (kt + 1 < KT) {
            stage((kt + 1) & 1, (kt + 1) * BK);
            asm volatile("cp.async.wait_group 1;\n" ::);
        } else {
            asm volatile("cp.async.wait_group 0;\n" ::);
        }
        __syncthreads();

        const __half* as = As[kt & 1];
        const __half* bs = Bs[kt & 1];

#pragma unroll
        for (int kk = 0; kk < 2; kk++) {           // two k16 steps
            const int kb = kk * 16 + koff;
            uint32_t af[2][4], bf[8][2];
#pragma unroll
            for (int mi = 0; mi < 2; mi++) {
                int m0 = wm * 32 + mi * 16 + grow;
                af[mi][0] = *(const uint32_t*)&as[(m0    ) * LSTR + kb    ];
                af[mi][1] = *(const uint32_t*)&as[(m0 + 8) * LSTR + kb    ];
                af[mi][2] = *(const uint32_t*)&as[(m0    ) * LSTR + kb + 8];
                af[mi][3] = *(const uint32_t*)&as[(m0 + 8) * LSTR + kb + 8];
            }
#pragma unroll
            for (int ni = 0; ni < 8; ni++) {
                int n0 = wn * 64 + ni * 8 + grow;
                bf[ni][0] = *(const uint32_t*)&bs[n0 * LSTR + kb    ];
                bf[ni][1] = *(const uint32_t*)&bs[n0 * LSTR + kb + 8];
            }
#pragma unroll
            for (int mi = 0; mi < 2; mi++)
#pragma unroll
                for (int ni = 0; ni < 8; ni++)
                    mma_f16(acc[mi][ni], af[mi], bf[ni]);
        }
        __syncthreads();
    }

    // ---- epilogue: bias + optional relu; fp16 or fp32 store ----
#pragma unroll
    for (int mi = 0; mi < 2; mi++) {
#pragma unroll
        for (int ni = 0; ni < 8; ni++) {
            int m = tileM + wm * 32 + mi * 16 + (lane >> 2);
            int n = tileN + wn * 64 + ni * 8 + ((lane & 3) << 1);
            float b0 = bias[n], b1 = bias[n + 1];
            float v0 = acc[mi][ni][0] + b0;
            float v1 = acc[mi][ni][1] + b1;
            float v2 = acc[mi][ni][2] + b0;
            float v3 = acc[mi][ni][3] + b1;
            if (relu) {
                v0 = fmaxf(v0, 0.0f); v1 = fmaxf(v1, 0.0f);
                v2 = fmaxf(v2, 0.0f); v3 = fmaxf(v3, 0.0f);
            }
            if (c_half) {
                __half* C = (__half*)Cv;
                *(__half2*)&C[(size_t)m * N + n]       = __floats2half2_rn(v0, v1);
                *(__half2*)&C[(size_t)(m + 8) * N + n] = __floats2half2_rn(v2, v3);
            } else {
                float* C = (float*)Cv;
                *(float2*)&C[(size_t)m * N + n]       = make_float2(v0, v1);
                *(float2*)&C[(size_t)(m + 8) * N + n] = make_float2(v2, v3);
            }
        }
    }
}

// ---- weight transpose + fp32->fp16: out[C,R] = half(in[R,C]^T) --------------
__global__ void transpose_h(const float* __restrict__ in, __half* __restrict__ out,
                            int R, int C)
{
    __shared__ float t[32][33];
    const int tx = threadIdx.x, ty = threadIdx.y;   // 32 x 8
    const int x0 = blockIdx.x * 32, y0 = blockIdx.y * 32;
#pragma unroll
    for (int i = 0; i < 32; i += 8)
        t[ty + i][tx] = in[(size_t)(y0 + ty + i) * C + x0 + tx];
    __syncthreads();
#pragma unroll
    for (int i = 0; i < 32; i += 8)
        out[(size_t)(x0 + ty + i) * R + y0 + tx] = __float2half_rn(t[tx][ty + i]);
}

// ---- elementwise fp32->fp16 -------------------------------------------------
__global__ void f2h_kernel(const float* __restrict__ in, __half* __restrict__ out, int n)
{
    int i = blockIdx.x * 256 + threadIdx.x;
    if (i < n) out[i] = __float2half_rn(in[i]);
}

// ---- gather spans + concat + relu (fp16) ------------------------------------
__global__ void gather_cat_kernel(const __half* __restrict__ srep, const __half* __restrict__ erep,
                                  const int* __restrict__ span, __half* __restrict__ cat)
{
    const int r  = blockIdx.x;     // 0..49151 (b*6144 + s)
    const int c8 = threadIdx.x;    // 0..191, 8 halves (16B) each
    const int b  = r / 6144;

    uint4 u;
    if (c8 < 96) {
        int i0 = span[((size_t)r << 1) + 0];
        u = *(const uint4*)&srep[((size_t)(b * 512 + i0)) * 768 + (c8 << 3)];
    } else {
        int i1 = span[((size_t)r << 1) + 1];
        u = *(const uint4*)&erep[((size_t)(b * 512 + i1)) * 768 + ((c8 - 96) << 3)];
    }
    const __half2 z = __floats2half2_rn(0.0f, 0.0f);
    __half2* p = (__half2*)&u;
#pragma unroll
    for (int j = 0; j < 4; j++) p[j] = __hmax2(p[j], z);
    *(uint4*)&cat[(size_t)r * 1536 + (c8 << 3)] = u;
}

extern "C" void kernel_launch(void* const* d_in, const int* in_sizes, int n_in,
                              void* d_out, int out_size)
{
    const float* h    = (const float*)d_in[0];
    const int*   span = (const int*)  d_in[1];
    const float* sw1  = (const float*)d_in[2];
    const float* sb1  = (const float*)d_in[3];
    const float* sw2  = (const float*)d_in[4];
    const float* sb2  = (const float*)d_in[5];
    const float* ew1  = (const float*)d_in[6];
    const float* eb1  = (const float*)d_in[7];
    const float* ew2  = (const float*)d_in[8];
    const float* eb2  = (const float*)d_in[9];
    const float* ow1  = (const float*)d_in[10];
    const float* ob1  = (const float*)d_in[11];
    const float* ow2  = (const float*)d_in[12];
    const float* ob2  = (const float*)d_in[13];
    float* out = (float*)d_out;

    __half *hidden, *srep, *erep, *cat, *hh;
    __half *sw1t, *ew1t, *ow1t, *sw2t, *ew2t, *ow2t;
    cudaGetSymbolAddress((void**)&hidden, g_hidden);
    cudaGetSymbolAddress((void**)&srep,   g_srep);
    cudaGetSymbolAddress((void**)&erep,   g_erep);
    cudaGetSymbolAddress((void**)&cat,    g_cat);
    cudaGetSymbolAddress((void**)&hh,     g_hh);
    cudaGetSymbolAddress((void**)&sw1t,   g_sw1t);
    cudaGetSymbolAddress((void**)&ew1t,   g_ew1t);
    cudaGetSymbolAddress((void**)&ow1t,   g_ow1t);
    cudaGetSymbolAddress((void**)&sw2t,   g_sw2t);
    cudaGetSymbolAddress((void**)&ew2t,   g_ew2t);
    cudaGetSymbolAddress((void**)&ow2t,   g_ow2t);

    const dim3 tb(32, 8);
    // weight transposes (+fp16 convert), and h convert
    transpose_h<<<dim3(3072 / 32,  768 / 32), tb>>>(sw1, sw1t,  768, 3072);
    transpose_h<<<dim3(3072 / 32,  768 / 32), tb>>>(ew1, ew1t,  768, 3072);
    transpose_h<<<dim3(3072 / 32, 1536 / 32), tb>>>(ow1, ow1t, 1536, 3072);
    transpose_h<<<dim3( 768 / 32, 3072 / 32), tb>>>(sw2, sw2t, 3072,  768);
    transpose_h<<<dim3( 768 / 32, 3072 / 32), tb>>>(ew2, ew2t, 3072,  768);
    transpose_h<<<dim3( 768 / 32, 3072 / 32), tb>>>(ow2, ow2t, 3072,  768);
    f2h_kernel<<<(3145728 + 255) / 256, 256>>>(h, hh, 3145728);

    const dim3 blk(256);
    // start projection
    gemm_f16<<<dim3(24, 32), blk>>>(hh,     sw1t, sb1, hidden, 4096, 3072,  768, 1, 1);
    gemm_f16<<<dim3( 6, 32), blk>>>(hidden, sw2t, sb2, srep,   4096,  768, 3072, 0, 1);
    // end projection
    gemm_f16<<<dim3(24, 32), blk>>>(hh,     ew1t, eb1, hidden, 4096, 3072,  768, 1, 1);
    gemm_f16<<<dim3( 6, 32), blk>>>(hidden, ew2t, eb2, erep,   4096,  768, 3072, 0, 1);
    // span gather + concat + relu
    gather_cat_kernel<<<49152, 192>>>(srep, erep, span, cat);
    // output projection
    gemm_f16<<<dim3(24, 384), blk>>>(cat,    ow1t, ob1, hidden, 49152, 3072, 1536, 1, 1);
    gemm_f16<<<dim3( 6, 384), blk>>>(hidden, ow2t, ob2, out,    49152,  768, 3072, 0, 0);
}

// round 6
// speedup vs baseline: 2.8455x; 1.3377x over previous
#include <cuda_runtime.h>
#include <cuda_fp16.h>
#include <cstdint>
#include <cstddef>

// ============================================================================
// SpanMarkerV1 on sm_100 (legacy tensor path): fp16 mma.sync m16n8k16, fp32 acc.
//   B=8, L=512, D=768, S=6144, H=3072
// 128x128x64 tiles, cp.async double buffer (dynamic smem), ldmatrix.x4 fragment
// loads, conflict-free stride-72-half smem, 2 CTAs/SM target.
// ============================================================================

#define BM 128
#define BN 128
#define BK 64
#define LSTR 72                       // halves; 144B row stride, conflict-free
#define STAGE_H (BM * LSTR)           // 9216 halves per operand tile
#define STAGE_ALL (2 * STAGE_H)       // A + B per stage
#define GSMEM_BYTES (2 * STAGE_ALL * 2)  // 73728 bytes

// -------- scratch (device globals; allocations are forbidden) ---------------
__device__ __half g_hidden[150994944ULL]; // 49152*3072 fp16 (302 MB), reused
__device__ __half g_srep[3145728ULL];     // 4096*768
__device__ __half g_erep[3145728ULL];     // 4096*768
__device__ __half g_cat[75497472ULL];     // 49152*1536 (151 MB)
__device__ __half g_hh[3145728ULL];       // h in fp16
__device__ __half g_sw1t[2359296ULL];     // [3072,768]  = W^T [N,K]
__device__ __half g_ew1t[2359296ULL];
__device__ __half g_ow1t[4718592ULL];     // [3072,1536]
__device__ __half g_sw2t[2359296ULL];     // [768,3072]
__device__ __half g_ew2t[2359296ULL];
__device__ __half g_ow2t[2359296ULL];

__device__ __forceinline__ void cp16(uint32_t smem_addr, const void* gmem_ptr) {
    asm volatile("cp.async.cg.shared.global [%0], [%1], 16;\n" :: "r"(smem_addr), "l"(gmem_ptr));
}

__device__ __forceinline__ void ldsm4(uint32_t* r, uint32_t addr) {
    asm volatile("ldmatrix.sync.aligned.m8n8.x4.shared.b16 {%0,%1,%2,%3}, [%4];"
                 : "=r"(r[0]), "=r"(r[1]), "=r"(r[2]), "=r"(r[3]) : "r"(addr));
}

__device__ __forceinline__ void mma_f16(float c[4], const uint32_t a[4], const uint32_t b[2]) {
    asm volatile(
        "mma.sync.aligned.m16n8k16.row.col.f32.f16.f16.f32 "
        "{%0,%1,%2,%3}, {%4,%5,%6,%7}, {%8,%9}, {%0,%1,%2,%3};\n"
        : "+f"(c[0]), "+f"(c[1]), "+f"(c[2]), "+f"(c[3])
        : "r"(a[0]), "r"(a[1]), "r"(a[2]), "r"(a[3]),
          "r"(b[0]), "r"(b[1]));
}

// ============================================================================
// C[M,N] = act(A[M,K] @ W + bias);  A fp16 [M,K], Bt = W^T fp16 [N,K].
// c_half: store fp16 (intermediates) else fp32 (final output).
// ============================================================================
__global__ __launch_bounds__(256, 2)
void gemm_f16(const __half* __restrict__ A, const __half* __restrict__ Bt,
              const float* __restrict__ bias, void* __restrict__ Cv,
              int M, int N, int K, int relu, int c_half)
{
    extern __shared__ __half sm[];
    const uint32_t sbase = (uint32_t)__cvta_generic_to_shared(sm);

    const int tid  = threadIdx.x;
    const int warp = tid >> 5;
    const int lane = tid & 31;
    const int wm = warp & 3;    // 32-row warp tile
    const int wn = warp >> 2;   // 64-col warp tile
    const int tileM = blockIdx.y * BM;
    const int tileN = blockIdx.x * BN;

    float acc[2][8][4];
#pragma unroll
    for (int mi = 0; mi < 2; mi++)
#pragma unroll
        for (int ni = 0; ni < 8; ni++)
#pragma unroll
            for (int j = 0; j < 4; j++) acc[mi][ni][j] = 0.0f;

    // ---- staging: per ktile, A and B each 128x64 halves = 1024 16B chunks --
    auto stage = [&](int s, int k0) {
        const uint32_t abase = sbase + s * (STAGE_ALL * 2);
        const uint32_t bbase = abase + STAGE_H * 2;
#pragma unroll
        for (int i = 0; i < 4; i++) {
            int ch  = tid + i * 256;
            int row = ch >> 3;
            int co  = (ch & 7) << 3;        // halves
            cp16(abase + (row * LSTR + co) * 2, A  + (size_t)(tileM + row) * K + k0 + co);
            cp16(bbase + (row * LSTR + co) * 2, Bt + (size_t)(tileN + row) * K + k0 + co);
        }
        asm volatile("cp.async.commit_group;\n" ::);
    };

    // ldmatrix per-lane source coords
    const int arow = lane & 15;            // A: lanes 0-15 -> rows, 16-31 -> +8 cols
    const int acol = (lane >> 4) << 3;
    const int bg   = lane >> 3;            // B: 4 groups of 8
    const int brow = ((bg >> 1) << 3) + (lane & 7);
    const int bcol = (bg & 1) << 3;

    const int KT = K / BK;
    stage(0, 0);

    for (int kt = 0; kt < KT; kt++) {
        if (kt + 1 < KT) {
            stage((kt + 1) & 1, (kt + 1) * BK);
            asm volatile("cp.async.wait_group 1;\n" ::);
        } else {
            asm volatile("cp.async.wait_group 0;\n" ::);
        }
        __syncthreads();

        const uint32_t abase = sbase + (kt & 1) * (STAGE_ALL * 2);
        const uint32_t bbase = abase + STAGE_H * 2;

#pragma unroll
        for (int kk = 0; kk < 4; kk++) {           // four k16 steps
            const int kb = kk << 4;
            uint32_t af[2][4], bf[8][2];
#pragma unroll
            for (int mi = 0; mi < 2; mi++) {
                int m0 = wm * 32 + mi * 16;
                ldsm4(af[mi], abase + ((m0 + arow) * LSTR + kb + acol) * 2);
            }
#pragma unroll
            for (int p = 0; p < 4; p++) {          // 2 n-octets per ldmatrix.x4
                int n0 = wn * 64 + p * 16;
                uint32_t r[4];
                ldsm4(r, bbase + ((n0 + brow) * LSTR + kb + bcol) * 2);
                bf[2 * p][0] = r[0]; bf[2 * p][1] = r[1];
                bf[2 * p + 1][0] = r[2]; bf[2 * p + 1][1] = r[3];
            }
#pragma unroll
            for (int mi = 0; mi < 2; mi++)
#pragma unroll
                for (int ni = 0; ni < 8; ni++)
                    mma_f16(acc[mi][ni], af[mi], bf[ni]);
        }
        __syncthreads();
    }

    // ---- epilogue: bias + optional relu; fp16 or fp32 store ----
#pragma unroll
    for (int mi = 0; mi < 2; mi++) {
#pragma unroll
        for (int ni = 0; ni < 8; ni++) {
            int m = tileM + wm * 32 + mi * 16 + (lane >> 2);
            int n = tileN + wn * 64 + ni * 8 + ((lane & 3) << 1);
            float b0 = bias[n], b1 = bias[n + 1];
            float v0 = acc[mi][ni][0] + b0;
            float v1 = acc[mi][ni][1] + b1;
            float v2 = acc[mi][ni][2] + b0;
            float v3 = acc[mi][ni][3] + b1;
            if (relu) {
                v0 = fmaxf(v0, 0.0f); v1 = fmaxf(v1, 0.0f);
                v2 = fmaxf(v2, 0.0f); v3 = fmaxf(v3, 0.0f);
            }
            if (c_half) {
                __half* C = (__half*)Cv;
                *(__half2*)&C[(size_t)m * N + n]       = __floats2half2_rn(v0, v1);
                *(__half2*)&C[(size_t)(m + 8) * N + n] = __floats2half2_rn(v2, v3);
            } else {
                float* C = (float*)Cv;
                *(float2*)&C[(size_t)m * N + n]       = make_float2(v0, v1);
                *(float2*)&C[(size_t)(m + 8) * N + n] = make_float2(v2, v3);
            }
        }
    }
}

// ---- weight transpose + fp32->fp16: out[C,R] = half(in[R,C]^T) --------------
__global__ void transpose_h(const float* __restrict__ in, __half* __restrict__ out,
                            int R, int C)
{
    __shared__ float t[32][33];
    const int tx = threadIdx.x, ty = threadIdx.y;   // 32 x 8
    const int x0 = blockIdx.x * 32, y0 = blockIdx.y * 32;
#pragma unroll
    for (int i = 0; i < 32; i += 8)
        t[ty + i][tx] = in[(size_t)(y0 + ty + i) * C + x0 + tx];
    __syncthreads();
#pragma unroll
    for (int i = 0; i < 32; i += 8)
        out[(size_t)(x0 + ty + i) * R + y0 + tx] = __float2half_rn(t[tx][ty + i]);
}

// ---- elementwise fp32->fp16 -------------------------------------------------
__global__ void f2h_kernel(const float* __restrict__ in, __half* __restrict__ out, int n)
{
    int i = blockIdx.x * 256 + threadIdx.x;
    if (i < n) out[i] = __float2half_rn(in[i]);
}

// ---- gather spans + concat + relu (fp16) ------------------------------------
__global__ void gather_cat_kernel(const __half* __restrict__ srep, const __half* __restrict__ erep,
                                  const int* __restrict__ span, __half* __restrict__ cat)
{
    const int r  = blockIdx.x;     // 0..49151 (b*6144 + s)
    const int c8 = threadIdx.x;    // 0..191, 8 halves (16B) each
    const int b  = r / 6144;

    uint4 u;
    if (c8 < 96) {
        int i0 = span[((size_t)r << 1) + 0];
        u = *(const uint4*)&srep[((size_t)(b * 512 + i0)) * 768 + (c8 << 3)];
    } else {
        int i1 = span[((size_t)r << 1) + 1];
        u = *(const uint4*)&erep[((size_t)(b * 512 + i1)) * 768 + ((c8 - 96) << 3)];
    }
    const __half2 z = __floats2half2_rn(0.0f, 0.0f);
    __half2* p = (__half2*)&u;
#pragma unroll
    for (int j = 0; j < 4; j++) p[j] = __hmax2(p[j], z);
    *(uint4*)&cat[(size_t)r * 1536 + (c8 << 3)] = u;
}

extern "C" void kernel_launch(void* const* d_in, const int* in_sizes, int n_in,
                              void* d_out, int out_size)
{
    const float* h    = (const float*)d_in[0];
    const int*   span = (const int*)  d_in[1];
    const float* sw1  = (const float*)d_in[2];
    const float* sb1  = (const float*)d_in[3];
    const float* sw2  = (const float*)d_in[4];
    const float* sb2  = (const float*)d_in[5];
    const float* ew1  = (const float*)d_in[6];
    const float* eb1  = (const float*)d_in[7];
    const float* ew2  = (const float*)d_in[8];
    const float* eb2  = (const float*)d_in[9];
    const float* ow1  = (const float*)d_in[10];
    const float* ob1  = (const float*)d_in[11];
    const float* ow2  = (const float*)d_in[12];
    const float* ob2  = (const float*)d_in[13];
    float* out = (float*)d_out;

    __half *hidden, *srep, *erep, *cat, *hh;
    __half *sw1t, *ew1t, *ow1t, *sw2t, *ew2t, *ow2t;
    cudaGetSymbolAddress((void**)&hidden, g_hidden);
    cudaGetSymbolAddress((void**)&srep,   g_srep);
    cudaGetSymbolAddress((void**)&erep,   g_erep);
    cudaGetSymbolAddress((void**)&cat,    g_cat);
    cudaGetSymbolAddress((void**)&hh,     g_hh);
    cudaGetSymbolAddress((void**)&sw1t,   g_sw1t);
    cudaGetSymbolAddress((void**)&ew1t,   g_ew1t);
    cudaGetSymbolAddress((void**)&ow1t,   g_ow1t);
    cudaGetSymbolAddress((void**)&sw2t,   g_sw2t);
    cudaGetSymbolAddress((void**)&ew2t,   g_ew2t);
    cudaGetSymbolAddress((void**)&ow2t,   g_ow2t);

    cudaFuncSetAttribute(gemm_f16, cudaFuncAttributeMaxDynamicSharedMemorySize, GSMEM_BYTES);

    const dim3 tb(32, 8);
    // weight transposes (+fp16 convert), and h convert
    transpose_h<<<dim3(3072 / 32,  768 / 32), tb>>>(sw1, sw1t,  768, 3072);
    transpose_h<<<dim3(3072 / 32,  768 / 32), tb>>>(ew1, ew1t,  768, 3072);
    transpose_h<<<dim3(3072 / 32, 1536 / 32), tb>>>(ow1, ow1t, 1536, 3072);
    transpose_h<<<dim3( 768 / 32, 3072 / 32), tb>>>(sw2, sw2t, 3072,  768);
    transpose_h<<<dim3( 768 / 32, 3072 / 32), tb>>>(ew2, ew2t, 3072,  768);
    transpose_h<<<dim3( 768 / 32, 3072 / 32), tb>>>(ow2, ow2t, 3072,  768);
    f2h_kernel<<<(3145728 + 255) / 256, 256>>>(h, hh, 3145728);

    const dim3 blk(256);
    // start projection
    gemm_f16<<<dim3(24, 32), blk, GSMEM_BYTES>>>(hh,     sw1t, sb1, hidden, 4096, 3072,  768, 1, 1);
    gemm_f16<<<dim3( 6, 32), blk, GSMEM_BYTES>>>(hidden, sw2t, sb2, srep,   4096,  768, 3072, 0, 1);
    // end projection
    gemm_f16<<<dim3(24, 32), blk, GSMEM_BYTES>>>(hh,     ew1t, eb1, hidden, 4096, 3072,  768, 1, 1);
    gemm_f16<<<dim3( 6, 32), blk, GSMEM_BYTES>>>(hidden, ew2t, eb2, erep,   4096,  768, 3072, 0, 1);
    // span gather + concat + relu
    gather_cat_kernel<<<49152, 192>>>(srep, erep, span, cat);
    // output projection
    gemm_f16<<<dim3(24, 384), blk, GSMEM_BYTES>>>(cat,    ow1t, ob1, hidden, 49152, 3072, 1536, 1, 1);
    gemm_f16<<<dim3( 6, 384), blk, GSMEM_BYTES>>>(hidden, ow2t, ob2, out,    49152,  768, 3072, 0, 0);
}